// round 12
// baseline (speedup 1.0000x reference)
#include <cuda_runtime.h>
#include <cstdint>

// WeightedAggregator: out[b,:] = sum_k (w[b,k]/sum_j w[b,j]) * features[idx[b,k],:]
// B = 50000, K = 16, D = 128 (fp32). neigh_idx is int32 (JAX demotes int64).
//
// R12: FOUR-phase index-windowed gather with L2-resident partial sums.
// Phase p gathers only rows with idx in [p*N/4, (p+1)*N/4): unique rows per
// phase ~51 MB + 26 MB partials fit the 126 MB L2 with slack, so within-phase
// repeat draws hit L2 (vs 29% baseline hit rate). Partial sums are stored and
// re-loaded with L2::evict_last so the dirty lines stay cache-resident across
// the back-to-back launches (L2 persists across kernel launches) and the
// intermediate round trips never touch DRAM. Each phase kernel keeps the
// 34-register R11 shape (one warp/row, 128-thread CTAs, flat grid).

#define K_NEIGH 16
#define FEAT_D 128

__device__ __forceinline__ uint64_t policy_evict_last() {
    uint64_t p;
    asm("createpolicy.fractional.L2::evict_last.b64 %0, 1.0;" : "=l"(p));
    return p;
}

__device__ __forceinline__ float4 ldg_hint(const float4* p, uint64_t pol) {
    float4 v;
    asm("ld.global.L2::cache_hint.v4.f32 {%0,%1,%2,%3}, [%4], %5;"
        : "=f"(v.x), "=f"(v.y), "=f"(v.z), "=f"(v.w)
        : "l"(p), "l"(pol));
    return v;
}

__device__ __forceinline__ void stg_hint(float4* p, float4 v, uint64_t pol) {
    asm volatile("st.global.L2::cache_hint.v4.f32 [%0], {%1,%2,%3,%4}, %5;"
                 :: "l"(p), "f"(v.x), "f"(v.y), "f"(v.z), "f"(v.w), "l"(pol)
                 : "memory");
}

template <bool FIRST, bool LAST>
__global__ __launch_bounds__(128)
void weighted_agg_phase(const float* __restrict__ features,
                        const float* __restrict__ neigh_w,
                        const int* __restrict__ neigh_idx,
                        float* __restrict__ out,
                        int B, int lo, int hi)
{
    const int gtid = blockIdx.x * blockDim.x + threadIdx.x;
    const int row  = gtid >> 5;          // warp id = output row
    const int lane = threadIdx.x & 31;
    if (row >= B) return;

    const uint64_t pol_last = policy_evict_last();

    // Lanes 0..15 hold this row's weight + index; others hold 0.
    float w  = 0.0f;
    int   ix = 0;
    if (lane < K_NEIGH) {
        w  = neigh_w  [row * K_NEIGH + lane];
        ix = neigh_idx[row * K_NEIGH + lane];
    }

    float4* outp = (float4*)out + (long long)row * (FEAT_D / 4) + lane;

    // Partial sum from prior phases (L2-resident via evict_last).
    float4 a0 = make_float4(0.f, 0.f, 0.f, 0.f);
    float4 a1 = make_float4(0.f, 0.f, 0.f, 0.f);
    if (!FIRST)
        a0 = ldg_hint((const float4*)outp, pol_last);

    // Warp-wide weight sum (only needed in the last phase; cheap).
    float s = w;
    #pragma unroll
    for (int off = 16; off > 0; off >>= 1)
        s += __shfl_xor_sync(0xffffffffu, s, off);
    const float inv = 1.0f / s;

    const float4* __restrict__ feat4 = (const float4*)features;

    // Predicated gather+accumulate; branch condition is warp-uniform.
    #pragma unroll
    for (int k = 0; k < K_NEIGH; k += 2) {
        const int   i0 = __shfl_sync(0xffffffffu, ix, k);
        const int   i1 = __shfl_sync(0xffffffffu, ix, k + 1);
        const float w0 = __shfl_sync(0xffffffffu, w, k);
        const float w1 = __shfl_sync(0xffffffffu, w, k + 1);
        if (i0 >= lo && i0 < hi) {
            const float4 f = __ldg(feat4 + (long long)i0 * (FEAT_D / 4) + lane);
            a0.x += w0 * f.x;  a0.y += w0 * f.y;
            a0.z += w0 * f.z;  a0.w += w0 * f.w;
        }
        if (i1 >= lo && i1 < hi) {
            const float4 f = __ldg(feat4 + (long long)i1 * (FEAT_D / 4) + lane);
            a1.x += w1 * f.x;  a1.y += w1 * f.y;
            a1.z += w1 * f.z;  a1.w += w1 * f.w;
        }
    }

    float4 r;
    if (LAST) {    // combine + normalize
        r.x = (a0.x + a1.x) * inv;
        r.y = (a0.y + a1.y) * inv;
        r.z = (a0.z + a1.z) * inv;
        r.w = (a0.w + a1.w) * inv;
        ((float4*)0, outp)[0] = r;   // plain store (final, write-once)
    } else {       // unnormalized partial, keep resident in L2
        r.x = a0.x + a1.x;  r.y = a0.y + a1.y;
        r.z = a0.z + a1.z;  r.w = a0.w + a1.w;
        stg_hint(outp, r, pol_last);
    }
}

extern "C" void kernel_launch(void* const* d_in, const int* in_sizes, int n_in,
                              void* d_out, int out_size)
{
    const float* features  = (const float*)d_in[0];   // [N_NODES, 128] fp32
    const float* neigh_w   = (const float*)d_in[1];   // [B, 16] fp32
    const int*   neigh_idx = (const int*)d_in[2];     // [B, 16] int32
    float*       out       = (float*)d_out;           // [B, 128] fp32

    const int B = in_sizes[1] / K_NEIGH;   // 50000
    const int N = in_sizes[0] / FEAT_D;    // 500000
    const int q = N / 4;                   // 125000-row windows (64 MB each)

    const int threads = 128;               // 4 warps/block -> 4 rows/block
    const int blocks  = (B * 32 + threads - 1) / threads;   // 12500

    weighted_agg_phase<true,  false><<<blocks, threads>>>(features, neigh_w, neigh_idx, out, B, 0,     q);
    weighted_agg_phase<false, false><<<blocks, threads>>>(features, neigh_w, neigh_idx, out, B, q,     2 * q);
    weighted_agg_phase<false, false><<<blocks, threads>>>(features, neigh_w, neigh_idx, out, B, 2 * q, 3 * q);
    weighted_agg_phase<false, true ><<<blocks, threads>>>(features, neigh_w, neigh_idx, out, B, 3 * q, N);
}

// round 13
// speedup vs baseline: 1.5945x; 1.5945x over previous
#include <cuda_runtime.h>

// WeightedAggregator: out[b,:] = sum_k (w[b,k]/sum_j w[b,j]) * features[idx[b,k],:]
// B = 50000, K = 16, D = 128 (fp32). One warp per output row; one float4 per lane.
// neigh_idx is int32 (JAX demotes int64 without x64 mode).
//
// FINAL (= R11): flat grid, one warp per row, 128-thread CTAs (34 regs ->
// 15 CTAs/SM = 60 resident warps), fully-coalesced LDG.128 gathers, warp-
// shuffle weight normalization folded into the epilogue.
//
// Measured: 52.6us (ncu), DRAM 77.4% of 8 TB/s. This is the random-512B-row
// gather roofline on this part: byte-reduction attempts (L2 eviction hints,
// 2- and 4-phase index windowing with L2-resident partials) all failed to
// raise the ~29% L2 hit rate of a uniform-random gather; latency/occupancy
// levers (forced MLP, persistent grid, block-size sweep) were neutral or
// negative except the 128-thread block shape kept here.

#define K_NEIGH 16
#define FEAT_D 128

__global__ __launch_bounds__(128)
void weighted_agg_kernel(const float* __restrict__ features,
                         const float* __restrict__ neigh_w,
                         const int* __restrict__ neigh_idx,
                         float* __restrict__ out,
                         int B)
{
    const int gtid = blockIdx.x * blockDim.x + threadIdx.x;
    const int row  = gtid >> 5;          // warp id = output row
    const int lane = threadIdx.x & 31;
    if (row >= B) return;

    // Lanes 0..15 hold this row's weight + index; others hold 0.
    float w  = 0.0f;
    int   ix = 0;
    if (lane < K_NEIGH) {
        w  = neigh_w  [row * K_NEIGH + lane];
        ix = neigh_idx[row * K_NEIGH + lane];
    }

    // Warp-wide weight sum (lanes >= 16 contribute 0).
    float s = w;
    #pragma unroll
    for (int off = 16; off > 0; off >>= 1)
        s += __shfl_xor_sync(0xffffffffu, s, off);
    const float inv = 1.0f / s;

    const float4* __restrict__ feat4 = (const float4*)features;

    // Gather: each warp-load is one 512B feature row = 4 x 128B lines,
    // fully coalesced. ptxas schedules loads/FMAs (34-reg version measured
    // identical to a forced-MLP asm variant).
    float4 f[K_NEIGH];
    #pragma unroll
    for (int k = 0; k < K_NEIGH; k++) {
        const int ik = __shfl_sync(0xffffffffu, ix, k);
        f[k] = __ldg(feat4 + (long long)ik * (FEAT_D / 4) + lane);
    }

    // Weighted accumulation, two independent FFMA chains.
    float4 a0 = make_float4(0.f, 0.f, 0.f, 0.f);
    float4 a1 = make_float4(0.f, 0.f, 0.f, 0.f);
    #pragma unroll
    for (int k = 0; k < K_NEIGH; k += 2) {
        const float w0 = __shfl_sync(0xffffffffu, w, k);
        const float w1 = __shfl_sync(0xffffffffu, w, k + 1);
        a0.x += w0 * f[k].x;     a1.x += w1 * f[k + 1].x;
        a0.y += w0 * f[k].y;     a1.y += w1 * f[k + 1].y;
        a0.z += w0 * f[k].z;     a1.z += w1 * f[k + 1].z;
        a0.w += w0 * f[k].w;     a1.w += w1 * f[k + 1].w;
    }

    float4 r;
    r.x = (a0.x + a1.x) * inv;
    r.y = (a0.y + a1.y) * inv;
    r.z = (a0.z + a1.z) * inv;
    r.w = (a0.w + a1.w) * inv;

    ((float4*)out)[(long long)row * (FEAT_D / 4) + lane] = r;
}

extern "C" void kernel_launch(void* const* d_in, const int* in_sizes, int n_in,
                              void* d_out, int out_size)
{
    const float* features  = (const float*)d_in[0];   // [N_NODES, 128] fp32
    const float* neigh_w   = (const float*)d_in[1];   // [B, 16] fp32
    const int*   neigh_idx = (const int*)d_in[2];     // [B, 16] int32
    float*       out       = (float*)d_out;           // [B, 128] fp32

    const int B = in_sizes[1] / K_NEIGH;   // 50000

    const int threads = 128;               // 4 warps/block -> 4 rows/block
    const int rows_per_block = threads / 32;
    const int blocks = (B + rows_per_block - 1) / rows_per_block;   // 12500

    weighted_agg_kernel<<<blocks, threads>>>(features, neigh_w, neigh_idx, out, B);
}

// round 14
// speedup vs baseline: 1.5974x; 1.0018x over previous
#include <cuda_runtime.h>

// WeightedAggregator: out[b,:] = sum_k (w[b,k]/sum_j w[b,j]) * features[idx[b,k],:]
// B = 50000, K = 16, D = 128 (fp32). neigh_idx is int32 (JAX demotes int64).
//
// R14: LDG.256 gather (sm_103a 256-bit loads). One warp per row; the warp is
// split into half-warps: lanes 0-15 load 32B slices of row ik[k], lanes 16-31
// of row ik[k+1] -> ONE ld.global.nc.v8.b32 fetches two full 512B feature
// rows (8 gather instructions instead of 16; 2x MLP per instruction at equal
// regs). Per-half-warp accumulators are combined with shfl_down(16); lanes
// 0-15 write the output row. Bytes and coalescing identical to the 52.6us
// baseline; this probes the LSU/L1tex request path.

#define K_NEIGH 16
#define FEAT_D 128

__device__ __forceinline__ void ldg_nc_v8(const float* p, float* r) {
    asm("ld.global.nc.v8.b32 {%0,%1,%2,%3,%4,%5,%6,%7}, [%8];"
        : "=f"(r[0]), "=f"(r[1]), "=f"(r[2]), "=f"(r[3]),
          "=f"(r[4]), "=f"(r[5]), "=f"(r[6]), "=f"(r[7])
        : "l"(p));
}

__global__ __launch_bounds__(128)
void weighted_agg_kernel(const float* __restrict__ features,
                         const float* __restrict__ neigh_w,
                         const int* __restrict__ neigh_idx,
                         float* __restrict__ out,
                         int B)
{
    const int gtid = blockIdx.x * blockDim.x + threadIdx.x;
    const int row  = gtid >> 5;          // warp id = output row
    const int lane = threadIdx.x & 31;
    if (row >= B) return;

    const int half = lane >> 4;          // 0: handles even k, 1: odd k
    const int m    = lane & 15;          // 32B slice index within the row

    // Lanes 0..15 hold this row's weight + index; others hold 0.
    float w  = 0.0f;
    int   ix = 0;
    if (lane < K_NEIGH) {
        w  = neigh_w  [row * K_NEIGH + lane];
        ix = neigh_idx[row * K_NEIGH + lane];
    }

    // Warp-wide weight sum (lanes >= 16 contribute 0).
    float s = w;
    #pragma unroll
    for (int off = 16; off > 0; off >>= 1)
        s += __shfl_xor_sync(0xffffffffu, s, off);
    const float inv = 1.0f / s;

    // Each half-warp accumulates its own k-chain over the same 8 columns
    // (floats [8m, 8m+8) of the output row).
    float acc[8];
    #pragma unroll
    for (int j = 0; j < 8; j++) acc[j] = 0.0f;

    #pragma unroll
    for (int k = 0; k < K_NEIGH; k += 2) {
        // Half 0 takes neighbor k, half 1 takes neighbor k+1.
        const int   ik = __shfl_sync(0xffffffffu, ix, k + half);
        const float wk = __shfl_sync(0xffffffffu, w,  k + half);

        float f[8];
        ldg_nc_v8(features + (long long)ik * FEAT_D + m * 8, f);

        #pragma unroll
        for (int j = 0; j < 8; j++)
            acc[j] += wk * f[j];
    }

    // Combine the two half-warp chains: lanes 0-15 receive lane+16's partial.
    #pragma unroll
    for (int j = 0; j < 8; j++)
        acc[j] += __shfl_down_sync(0xffffffffu, acc[j], 16);

    if (lane < 16) {
        float4 s0, s1;
        s0.x = acc[0] * inv;  s0.y = acc[1] * inv;
        s0.z = acc[2] * inv;  s0.w = acc[3] * inv;
        s1.x = acc[4] * inv;  s1.y = acc[5] * inv;
        s1.z = acc[6] * inv;  s1.w = acc[7] * inv;
        float4* outp = (float4*)out + (long long)row * (FEAT_D / 4) + m * 2;
        outp[0] = s0;
        outp[1] = s1;
    }
}

extern "C" void kernel_launch(void* const* d_in, const int* in_sizes, int n_in,
                              void* d_out, int out_size)
{
    const float* features  = (const float*)d_in[0];   // [N_NODES, 128] fp32
    const float* neigh_w   = (const float*)d_in[1];   // [B, 16] fp32
    const int*   neigh_idx = (const int*)d_in[2];     // [B, 16] int32
    float*       out       = (float*)d_out;           // [B, 128] fp32

    const int B = in_sizes[1] / K_NEIGH;   // 50000

    const int threads = 128;               // 4 warps/block -> 4 rows/block
    const int rows_per_block = threads / 32;
    const int blocks = (B + rows_per_block - 1) / rows_per_block;   // 12500

    weighted_agg_kernel<<<blocks, threads>>>(features, neigh_w, neigh_idx, out, B);
}